// round 14
// baseline (speedup 1.0000x reference)
#include <cuda_runtime.h>
#include <stdint.h>

// ============================================================================
// ImpulseNoise — bit-exact JAX (threefry_partitionable) salt & pepper.
// key=(0,42); k_flip = tf20(key,(0,0)); k_salt = tf20(key,(0,1))
// bits(i) = fold(tf20(k, (0, i)));  u = (bits>>9)*2^-23
// u <= 0.09f  <=>  bits <= (754974<<9)|511     (rel_err=0 verified R2-R13)
// u <= 0.5    <=>  bits <= 0x800001FF
//
// R14 = R13 hash math (k=2 rot-29 mul-pairs, counter pre-add; 158.3us)
// restructured as ROUND-LOCKSTEP over the 8 flip chains (SoA x0[8]/x1[8],
// fully unrolled chain-minor loops). R13 showed alu 85.5 / issue 81.1 with
// nothing saturated -> latency exposure from under-interleaved serial
// chains. Lockstep gives every instruction 7 independent siblings.
// Image stores moved BEFORE hashing (frees the float4 regs);
// launch_bounds(256,8) pins regs<=32 (R7/R11-proven spill-free).
// Salt hashes remain warp-ballot-compacted (~0.09 hashes/elem).
// ============================================================================

struct U2c { unsigned a, b; };

constexpr U2c threefry20_host(unsigned k0, unsigned k1, unsigned x0, unsigned x1) {
    unsigned ks2 = k0 ^ k1 ^ 0x1BD11BDAu;
    x0 += k0; x1 += k1;
#define TFR_H(r) { x0 += x1; x1 = (x1 << (r)) | (x1 >> (32 - (r))); x1 ^= x0; }
    TFR_H(13) TFR_H(15) TFR_H(26) TFR_H(6)
    x0 += k1;  x1 += ks2 + 1u;
    TFR_H(17) TFR_H(29) TFR_H(16) TFR_H(24)
    x0 += ks2; x1 += k0 + 2u;
    TFR_H(13) TFR_H(15) TFR_H(26) TFR_H(6)
    x0 += k0;  x1 += k1 + 3u;
    TFR_H(17) TFR_H(29) TFR_H(16) TFR_H(24)
    x0 += k1;  x1 += ks2 + 4u;
    TFR_H(13) TFR_H(15) TFR_H(26) TFR_H(6)
    x0 += ks2; x1 += k0 + 5u;
#undef TFR_H
    return U2c{x0, x1};
}

constexpr U2c KFLIP = threefry20_host(0u, 42u, 0u, 0u);
constexpr U2c KSALT = threefry20_host(0u, 42u, 0u, 1u);

constexpr unsigned N_TOTAL = 64u * 3u * 512u * 512u;   // 50331648
constexpr unsigned FLIP_T  = (754974u << 9) | 511u;    // u <= 0.09f
constexpr unsigned SALT_T  = 0x800001FFu;              // u <= 0.5f

// Adds forced to IMAD (fma pipe): d = a*one + b.
__device__ __forceinline__ unsigned madr(unsigned a, unsigned one, unsigned b) {
    unsigned d;
    asm("mad.lo.u32 %0, %1, %2, %3;" : "=r"(d) : "r"(a), "r"(one), "r"(b));
    return d;
}
template <unsigned IMM>
__device__ __forceinline__ unsigned madi(unsigned a, unsigned one) {
    unsigned d;
    asm("mad.lo.u32 %0, %1, %2, %3;" : "=r"(d) : "r"(a), "r"(one), "n"(IMM));
    return d;
}

// ---- scalar hash (salt path only; R13-identical) ---------------------------
#define TFR_S(r) { x0 = madr(x0, one, x1); x1 = __funnelshift_l(x1, x1, (r)); x1 ^= x0; }
#define TFR_M2(mr) { x0 = madr(x0, one, x1);            \
    unsigned lo = x1 * (mr);                             \
    unsigned hi = __umulhi(x1, (mr));                    \
    x1 = (lo | hi) ^ x0; }
template <unsigned K0, unsigned K1>
__device__ __forceinline__ unsigned tf20_fold_pre(unsigned x1in, unsigned one,
                                                  unsigned m29) {
    constexpr unsigned KS2 = K0 ^ K1 ^ 0x1BD11BDAu;
    unsigned x1 = x1in;
    unsigned x0 = madi<K0>(x1, one);
    x1 = __funnelshift_l(x1, x1, 13); x1 ^= x0;
    TFR_S(15) TFR_S(26) TFR_S(6)
    x0 = madi<K1>(x0, one);   x1 = madi<KS2 + 1u>(x1, one);
    TFR_S(17) TFR_M2(m29) TFR_S(16) TFR_S(24)
    x0 = madi<KS2>(x0, one);  x1 = madi<K0 + 2u>(x1, one);
    TFR_S(13) TFR_S(15) TFR_S(26) TFR_S(6)
    x0 = madi<K0>(x0, one);   x1 = madi<K1 + 3u>(x1, one);
    TFR_S(17) TFR_M2(m29) TFR_S(16) TFR_S(24)
    x0 = madi<K1>(x0, one);   x1 = madi<KS2 + 4u>(x1, one);
    TFR_S(13) TFR_S(15) TFR_S(26) TFR_S(6)
    x0 = madi<KS2>(x0, one);  x1 = madi<K0 + 5u>(x1, one);
    return x0 ^ x1;
}
#undef TFR_S
#undef TFR_M2

// ---- lockstep 8-chain macros (flip path) -----------------------------------
#define L_ROUND_S(r)                                                   \
    _Pragma("unroll") for (int s = 0; s < 8; ++s) {                     \
        X0[s] = madr(X0[s], one, X1[s]);                                \
        X1[s] = __funnelshift_l(X1[s], X1[s], (r)) ^ X0[s]; }
#define L_ROUND_M2(mr)                                                 \
    _Pragma("unroll") for (int s = 0; s < 8; ++s) {                     \
        X0[s] = madr(X0[s], one, X1[s]);                                \
        unsigned lo = X1[s] * (mr);                                     \
        unsigned hi = __umulhi(X1[s], (mr));                            \
        X1[s] = (lo | hi) ^ X0[s]; }
#define L_INJ(C0, C1)                                                  \
    _Pragma("unroll") for (int s = 0; s < 8; ++s) {                     \
        X0[s] = madi<(C0)>(X0[s], one);                                 \
        X1[s] = madi<(C1)>(X1[s], one); }

// 8 elements per thread; warp covers 256 consecutive elements.
__global__ void __launch_bounds__(256, 8)
impulse_noise_kernel(const float* __restrict__ img, float* __restrict__ out,
                     unsigned one) {
    constexpr unsigned K0  = KFLIP.a, K1 = KFLIP.b;
    constexpr unsigned KS2 = K0 ^ K1 ^ 0x1BD11BDAu;
    unsigned m29 = one << 29;   // opaque 2^29 multiplier

    unsigned gwarp = (blockIdx.x * 256u + threadIdx.x) >> 5;
    unsigned lane  = threadIdx.x & 31u;
    unsigned base  = gwarp * 256u;
    unsigned i0 = base + 4u * lane;
    unsigned i1 = base + 128u + 4u * lane;

    // Load + store raw values up-front (frees these regs through the hashes;
    // flipped slots are overwritten after the __syncwarp fence below).
    float4 v0 = *reinterpret_cast<const float4*>(img + i0);
    float4 v1 = *reinterpret_cast<const float4*>(img + i1);
    *reinterpret_cast<float4*>(out + i0) = v0;
    *reinterpret_cast<float4*>(out + i1) = v1;

    // Hoisted counter bases (R13 trim).
    unsigned b0f = madi<K1>(i0, one);
    unsigned b1f = madi<K1>(i1, one);

    // ---- 8 flip hashes in round-lockstep (SoA) ----
    unsigned X0[8], X1[8];
#pragma unroll
    for (int s = 0; s < 8; ++s) {
        unsigned x1 = (s < 4) ? (b0f + (unsigned)s) : (b1f + (unsigned)(s - 4));
        unsigned x0 = madi<K0>(x1, one);                 // round-1 add
        X1[s] = __funnelshift_l(x1, x1, 13) ^ x0;        // finish round 1
        X0[s] = x0;
    }
    L_ROUND_S(15) L_ROUND_S(26) L_ROUND_S(6)             // rounds 2-4
    L_INJ(K1, KS2 + 1u)
    L_ROUND_S(17) L_ROUND_M2(m29) L_ROUND_S(16) L_ROUND_S(24)   // 5-8
    L_INJ(KS2, K0 + 2u)
    L_ROUND_S(13) L_ROUND_S(15) L_ROUND_S(26) L_ROUND_S(6)      // 9-12
    L_INJ(K0, K1 + 3u)
    L_ROUND_S(17) L_ROUND_M2(m29) L_ROUND_S(16) L_ROUND_S(24)   // 13-16
    L_INJ(K1, KS2 + 4u)
    L_ROUND_S(13) L_ROUND_S(15) L_ROUND_S(26) L_ROUND_S(6)      // 17-20

    // Final injection folded into the output fold + threshold compare.
    bool fl[8];
#pragma unroll
    for (int s = 0; s < 8; ++s)
        fl[s] = ((X0[s] + KS2) ^ (X1[s] + (K0 + 5u))) <= FLIP_T;

    // Warp-uniform flip masks + prefix counts.
    unsigned m[8], cum[9];
    cum[0] = 0;
#pragma unroll
    for (int s = 0; s < 8; ++s) {
        m[s] = __ballot_sync(0xFFFFFFFFu, fl[s]);
        cum[s + 1] = cum[s] + (unsigned)__popc(m[s]);
    }
    unsigned nf = cum[8];

    __syncwarp();  // owner stores happen-before compacted overwrites

    // Compacted salt passes: 32 flips served per pass (~1 pass typical).
    for (unsigned start = 0; start < nf; start += 32u) {
        unsigned r = start + lane;
        if (r < nf) {
            unsigned mm = m[0], rbase = 0u, eoff = 0u;
#pragma unroll
            for (int w = 1; w < 8; ++w) {
                if (r >= cum[w]) {
                    mm = m[w];
                    rbase = cum[w];
                    eoff = (w < 4) ? (unsigned)w : (unsigned)w + 124u;
                }
            }
            unsigned rr = r - rbase;
            unsigned pos = 0u, c;
            c = (unsigned)__popc(mm & 0xFFFFu); if (rr >= c) { rr -= c; pos += 16u; mm >>= 16; }
            c = (unsigned)__popc(mm & 0xFFu);   if (rr >= c) { rr -= c; pos += 8u;  mm >>= 8; }
            c = (unsigned)__popc(mm & 0xFu);    if (rr >= c) { rr -= c; pos += 4u;  mm >>= 4; }
            c = (unsigned)__popc(mm & 0x3u);    if (rr >= c) { rr -= c; pos += 2u;  mm >>= 2; }
            c = mm & 1u;                        if (rr >= c) { pos += 1u; }

            unsigned gi = base + 4u * pos + eoff;
            unsigned bs = tf20_fold_pre<KSALT.a, KSALT.b>(
                madi<KSALT.b>(gi, one), one, m29);
            out[gi] = (bs <= SALT_T) ? 1.0f : 0.0f;
        }
    }
}

extern "C" void kernel_launch(void* const* d_in, const int* in_sizes, int n_in,
                              void* d_out, int out_size) {
    const float* img = (const float*)d_in[0];
    float* out = (float*)d_out;
    constexpr unsigned threads = N_TOTAL / 8u;    // 6291456
    constexpr unsigned blocks  = threads / 256u;  // 24576
    impulse_noise_kernel<<<blocks, 256>>>(img, out, 1u);
}

// round 15
// speedup vs baseline: 1.0046x; 1.0046x over previous
#include <cuda_runtime.h>
#include <stdint.h>

// ============================================================================
// ImpulseNoise — bit-exact JAX (threefry_partitionable) salt & pepper.
// key=(0,42); k_flip = tf20(key,(0,0)); k_salt = tf20(key,(0,1))
// bits(i) = fold(tf20(k, (0, i)));  u = (bits>>9)*2^-23
// u <= 0.09f  <=>  bits <= (754974<<9)|511     (rel_err=0 verified R2-R14)
// u <= 0.5    <=>  bits <= 0x800001FF
//
// R15 = R13 champion (158.3us) + round 10 converted to mul-pair (rot 15).
// Calibrated model: alu-time = 2*(41-k), stream-time = 74+k per hash;
// k=3 minimizes max(76,77)=77 vs R13's k=2 max(78,76)=78.
// R14 falsified the latency theory (lockstep neutral) -> R13 structure kept:
// hash first / store after (hides LDG->STG), ballot-compacted salt.
// ============================================================================

struct U2c { unsigned a, b; };

constexpr U2c threefry20_host(unsigned k0, unsigned k1, unsigned x0, unsigned x1) {
    unsigned ks2 = k0 ^ k1 ^ 0x1BD11BDAu;
    x0 += k0; x1 += k1;
#define TFR_H(r) { x0 += x1; x1 = (x1 << (r)) | (x1 >> (32 - (r))); x1 ^= x0; }
    TFR_H(13) TFR_H(15) TFR_H(26) TFR_H(6)
    x0 += k1;  x1 += ks2 + 1u;
    TFR_H(17) TFR_H(29) TFR_H(16) TFR_H(24)
    x0 += ks2; x1 += k0 + 2u;
    TFR_H(13) TFR_H(15) TFR_H(26) TFR_H(6)
    x0 += k0;  x1 += k1 + 3u;
    TFR_H(17) TFR_H(29) TFR_H(16) TFR_H(24)
    x0 += k1;  x1 += ks2 + 4u;
    TFR_H(13) TFR_H(15) TFR_H(26) TFR_H(6)
    x0 += ks2; x1 += k0 + 5u;
#undef TFR_H
    return U2c{x0, x1};
}

constexpr U2c KFLIP = threefry20_host(0u, 42u, 0u, 0u);
constexpr U2c KSALT = threefry20_host(0u, 42u, 0u, 1u);

constexpr unsigned N_TOTAL = 64u * 3u * 512u * 512u;   // 50331648
constexpr unsigned FLIP_T  = (754974u << 9) | 511u;    // u <= 0.09f
constexpr unsigned SALT_T  = 0x800001FFu;              // u <= 0.5f

// Adds forced to IMAD (fma pipe): d = a*one + b  (R4-proven placement).
__device__ __forceinline__ unsigned madr(unsigned a, unsigned one, unsigned b) {
    unsigned d;
    asm("mad.lo.u32 %0, %1, %2, %3;" : "=r"(d) : "r"(a), "r"(one), "r"(b));
    return d;
}
template <unsigned IMM>
__device__ __forceinline__ unsigned madi(unsigned a, unsigned one) {
    unsigned d;
    asm("mad.lo.u32 %0, %1, %2, %3;" : "=r"(d) : "r"(a), "r"(one), "n"(IMM));
    return d;
}

// SHF round: add (fma) + funnel-rotate (alu) + xor (alu).
#define TFR_S(r) { x0 = madr(x0, one, x1); x1 = __funnelshift_l(x1, x1, (r)); x1 ^= x0; }
// MUL-PAIR round: add (fma) + mullo,mulhi (2x single-reg IMAD, fma) +
// fused (lo|hi)^x0 (ONE LOP3, alu).
#define TFR_M2(mr) { x0 = madr(x0, one, x1);            \
    unsigned lo = x1 * (mr);                             \
    unsigned hi = __umulhi(x1, (mr));                    \
    x1 = (lo | hi) ^ x0; }

// Threefry-2x32-20 with x1 counter-init PRE-ADDED (x1in = i + K1).
// Mul-pair rounds: 6 (rot29), 10 (rot15), 14 (rot29). Returns x0^x1.
template <unsigned K0, unsigned K1>
__device__ __forceinline__ unsigned tf20_fold_pre(unsigned x1in, unsigned one,
                                                  unsigned m15, unsigned m29) {
    constexpr unsigned KS2 = K0 ^ K1 ^ 0x1BD11BDAu;
    unsigned x1 = x1in;
    unsigned x0 = madi<K0>(x1, one);                 // round-1 add (x0_init=K0)
    x1 = __funnelshift_l(x1, x1, 13); x1 ^= x0;      // finish round 1
    TFR_S(15) TFR_S(26) TFR_S(6)                     // rounds 2,3,4
    x0 = madi<K1>(x0, one);   x1 = madi<KS2 + 1u>(x1, one);
    TFR_S(17) TFR_M2(m29) TFR_S(16) TFR_S(24)        // rounds 5,6,7,8
    x0 = madi<KS2>(x0, one);  x1 = madi<K0 + 2u>(x1, one);
    TFR_S(13) TFR_M2(m15) TFR_S(26) TFR_S(6)         // rounds 9,10,11,12
    x0 = madi<K0>(x0, one);   x1 = madi<K1 + 3u>(x1, one);
    TFR_S(17) TFR_M2(m29) TFR_S(16) TFR_S(24)        // rounds 13,14,15,16
    x0 = madi<K1>(x0, one);   x1 = madi<KS2 + 4u>(x1, one);
    TFR_S(13) TFR_S(15) TFR_S(26) TFR_S(6)           // rounds 17-20
    x0 = madi<KS2>(x0, one);  x1 = madi<K0 + 5u>(x1, one);
    return x0 ^ x1;
}
#undef TFR_S
#undef TFR_M2

// 8 elements per thread; warp covers 256 consecutive elements.
__global__ void __launch_bounds__(256)
impulse_noise_kernel(const float* __restrict__ img, float* __restrict__ out,
                     unsigned one) {
    unsigned m15 = one << 15, m29 = one << 29;   // opaque 2^r multipliers

    unsigned gwarp = (blockIdx.x * 256u + threadIdx.x) >> 5;
    unsigned lane  = threadIdx.x & 31u;
    unsigned base  = gwarp * 256u;
    unsigned i0 = base + 4u * lane;
    unsigned i1 = base + 128u + 4u * lane;

    float4 v0 = *reinterpret_cast<const float4*>(img + i0);
    float4 v1 = *reinterpret_cast<const float4*>(img + i1);

    // Hoisted counter bases: each chain's x1 init is one add from these.
    unsigned b0f = madi<KFLIP.b>(i0, one);   // i0 + K1_flip
    unsigned b1f = madi<KFLIP.b>(i1, one);   // i1 + K1_flip

    // Mandatory flip hashes (8 independent chains for ILP).
    bool fl[8];
#pragma unroll
    for (int s = 0; s < 4; ++s)
        fl[s] = tf20_fold_pre<KFLIP.a, KFLIP.b>(b0f + (unsigned)s, one, m15, m29) <= FLIP_T;
#pragma unroll
    for (int s = 0; s < 4; ++s)
        fl[4 + s] = tf20_fold_pre<KFLIP.a, KFLIP.b>(b1f + (unsigned)s, one, m15, m29) <= FLIP_T;

    // Owners store raw values AFTER hashing (hides LDG->STG latency under
    // the hash stream); flipped slots overwritten after the fence.
    *reinterpret_cast<float4*>(out + i0) = v0;
    *reinterpret_cast<float4*>(out + i1) = v1;

    // Warp-uniform flip masks + prefix counts.
    unsigned m[8], cum[9];
    cum[0] = 0;
#pragma unroll
    for (int s = 0; s < 8; ++s) {
        m[s] = __ballot_sync(0xFFFFFFFFu, fl[s]);
        cum[s + 1] = cum[s] + (unsigned)__popc(m[s]);
    }
    unsigned nf = cum[8];

    __syncwarp();  // owner stores happen-before compacted overwrites

    // Compacted salt passes: 32 flips served per pass (~1 pass typical).
    for (unsigned start = 0; start < nf; start += 32u) {
        unsigned r = start + lane;
        if (r < nf) {
            unsigned mm = m[0], rbase = 0u, eoff = 0u;
#pragma unroll
            for (int w = 1; w < 8; ++w) {
                if (r >= cum[w]) {
                    mm = m[w];
                    rbase = cum[w];
                    eoff = (w < 4) ? (unsigned)w : (unsigned)w + 124u;
                }
            }
            unsigned rr = r - rbase;
            unsigned pos = 0u, c;
            c = (unsigned)__popc(mm & 0xFFFFu); if (rr >= c) { rr -= c; pos += 16u; mm >>= 16; }
            c = (unsigned)__popc(mm & 0xFFu);   if (rr >= c) { rr -= c; pos += 8u;  mm >>= 8; }
            c = (unsigned)__popc(mm & 0xFu);    if (rr >= c) { rr -= c; pos += 4u;  mm >>= 4; }
            c = (unsigned)__popc(mm & 0x3u);    if (rr >= c) { rr -= c; pos += 2u;  mm >>= 2; }
            c = mm & 1u;                        if (rr >= c) { pos += 1u; }

            unsigned gi = base + 4u * pos + eoff;
            unsigned bs = tf20_fold_pre<KSALT.a, KSALT.b>(
                madi<KSALT.b>(gi, one), one, m15, m29);
            out[gi] = (bs <= SALT_T) ? 1.0f : 0.0f;
        }
    }
}

extern "C" void kernel_launch(void* const* d_in, const int* in_sizes, int n_in,
                              void* d_out, int out_size) {
    const float* img = (const float*)d_in[0];
    float* out = (float*)d_out;
    constexpr unsigned threads = N_TOTAL / 8u;    // 6291456
    constexpr unsigned blocks  = threads / 256u;  // 24576
    impulse_noise_kernel<<<blocks, 256>>>(img, out, 1u);
}

// round 16
// speedup vs baseline: 1.0156x; 1.0109x over previous
#include <cuda_runtime.h>
#include <stdint.h>

// ============================================================================
// ImpulseNoise — bit-exact JAX (threefry_partitionable) salt & pepper.
// key=(0,42); k_flip = tf20(key,(0,0)); k_salt = tf20(key,(0,1))
// bits(i) = fold(tf20(k, (0, i)));  u = (bits>>9)*2^-23
// u <= 0.09f  <=>  bits <= (754974<<9)|511     (rel_err=0 verified R2-R15)
// u <= 0.5    <=>  bits <= 0x800001FF
//
// R16 = R13 CHAMPION VERBATIM (re-verification run).
// Design-space summary (R4-R15 sweep, all calibrated):
//   - k=2 mul-pair rotates (rounds 6,14 rot29) = measured optimum of the
//     alu-relief vs stream-growth tradeoff (k=0:159.3, k=2:158.3,
//     k=3:159.7, k=5:162.9).
//   - all round adds forced to IMAD (fma pipe) via mad.lo with opaque `one`.
//   - counter pre-add hoisted out of the 4-chain loops.
//   - hash-first / store-after (R14 proved early stores cost ~1%).
//   - salt hashes warp-ballot-compacted: 0.09 hashes/elem instead of 1.0.
//   - wide-mul rotates, injection folds, manual lockstep, occupancy pinning:
//     all tested, all neutral or regressions. This config is the floor
//     (~2% above the structural issue-band limit of ~155us).
// ============================================================================

struct U2c { unsigned a, b; };

constexpr U2c threefry20_host(unsigned k0, unsigned k1, unsigned x0, unsigned x1) {
    unsigned ks2 = k0 ^ k1 ^ 0x1BD11BDAu;
    x0 += k0; x1 += k1;
#define TFR_H(r) { x0 += x1; x1 = (x1 << (r)) | (x1 >> (32 - (r))); x1 ^= x0; }
    TFR_H(13) TFR_H(15) TFR_H(26) TFR_H(6)
    x0 += k1;  x1 += ks2 + 1u;
    TFR_H(17) TFR_H(29) TFR_H(16) TFR_H(24)
    x0 += ks2; x1 += k0 + 2u;
    TFR_H(13) TFR_H(15) TFR_H(26) TFR_H(6)
    x0 += k0;  x1 += k1 + 3u;
    TFR_H(17) TFR_H(29) TFR_H(16) TFR_H(24)
    x0 += k1;  x1 += ks2 + 4u;
    TFR_H(13) TFR_H(15) TFR_H(26) TFR_H(6)
    x0 += ks2; x1 += k0 + 5u;
#undef TFR_H
    return U2c{x0, x1};
}

constexpr U2c KFLIP = threefry20_host(0u, 42u, 0u, 0u);
constexpr U2c KSALT = threefry20_host(0u, 42u, 0u, 1u);

constexpr unsigned N_TOTAL = 64u * 3u * 512u * 512u;   // 50331648
constexpr unsigned FLIP_T  = (754974u << 9) | 511u;    // u <= 0.09f
constexpr unsigned SALT_T  = 0x800001FFu;              // u <= 0.5f

// Adds forced to IMAD (fma pipe): d = a*one + b.
__device__ __forceinline__ unsigned madr(unsigned a, unsigned one, unsigned b) {
    unsigned d;
    asm("mad.lo.u32 %0, %1, %2, %3;" : "=r"(d) : "r"(a), "r"(one), "r"(b));
    return d;
}
template <unsigned IMM>
__device__ __forceinline__ unsigned madi(unsigned a, unsigned one) {
    unsigned d;
    asm("mad.lo.u32 %0, %1, %2, %3;" : "=r"(d) : "r"(a), "r"(one), "n"(IMM));
    return d;
}

// SHF round: add (fma) + funnel-rotate (alu) + xor (alu).
#define TFR_S(r) { x0 = madr(x0, one, x1); x1 = __funnelshift_l(x1, x1, (r)); x1 ^= x0; }
// MUL-PAIR round: add (fma) + mullo,mulhi (2x single-reg IMAD, fma) +
// fused (lo|hi)^x0 (ONE LOP3, alu).
#define TFR_M2(mr) { x0 = madr(x0, one, x1);            \
    unsigned lo = x1 * (mr);                             \
    unsigned hi = __umulhi(x1, (mr));                    \
    x1 = (lo | hi) ^ x0; }

// Threefry-2x32-20 with x1 counter-init PRE-ADDED (x1in = i + K1).
// Mul-pair rounds: 6 and 14 (rot 29). Returns x0^x1.
template <unsigned K0, unsigned K1>
__device__ __forceinline__ unsigned tf20_fold_pre(unsigned x1in, unsigned one,
                                                  unsigned m29) {
    constexpr unsigned KS2 = K0 ^ K1 ^ 0x1BD11BDAu;
    unsigned x1 = x1in;
    unsigned x0 = madi<K0>(x1, one);                 // round-1 add (x0_init=K0)
    x1 = __funnelshift_l(x1, x1, 13); x1 ^= x0;      // finish round 1
    TFR_S(15) TFR_S(26) TFR_S(6)                     // rounds 2,3,4
    x0 = madi<K1>(x0, one);   x1 = madi<KS2 + 1u>(x1, one);
    TFR_S(17) TFR_M2(m29) TFR_S(16) TFR_S(24)        // rounds 5,6,7,8
    x0 = madi<KS2>(x0, one);  x1 = madi<K0 + 2u>(x1, one);
    TFR_S(13) TFR_S(15) TFR_S(26) TFR_S(6)           // rounds 9-12
    x0 = madi<K0>(x0, one);   x1 = madi<K1 + 3u>(x1, one);
    TFR_S(17) TFR_M2(m29) TFR_S(16) TFR_S(24)        // rounds 13,14,15,16
    x0 = madi<K1>(x0, one);   x1 = madi<KS2 + 4u>(x1, one);
    TFR_S(13) TFR_S(15) TFR_S(26) TFR_S(6)           // rounds 17-20
    x0 = madi<KS2>(x0, one);  x1 = madi<K0 + 5u>(x1, one);
    return x0 ^ x1;
}
#undef TFR_S
#undef TFR_M2

// 8 elements per thread; warp covers 256 consecutive elements.
__global__ void __launch_bounds__(256)
impulse_noise_kernel(const float* __restrict__ img, float* __restrict__ out,
                     unsigned one) {
    unsigned m29 = one << 29;   // opaque 2^29 multiplier

    unsigned gwarp = (blockIdx.x * 256u + threadIdx.x) >> 5;
    unsigned lane  = threadIdx.x & 31u;
    unsigned base  = gwarp * 256u;
    unsigned i0 = base + 4u * lane;
    unsigned i1 = base + 128u + 4u * lane;

    float4 v0 = *reinterpret_cast<const float4*>(img + i0);
    float4 v1 = *reinterpret_cast<const float4*>(img + i1);

    // Hoisted counter bases: each chain's x1 init is one add from these.
    unsigned b0f = madi<KFLIP.b>(i0, one);   // i0 + K1_flip
    unsigned b1f = madi<KFLIP.b>(i1, one);   // i1 + K1_flip

    // Mandatory flip hashes (8 independent chains for ILP).
    bool fl[8];
#pragma unroll
    for (int s = 0; s < 4; ++s)
        fl[s] = tf20_fold_pre<KFLIP.a, KFLIP.b>(b0f + (unsigned)s, one, m29) <= FLIP_T;
#pragma unroll
    for (int s = 0; s < 4; ++s)
        fl[4 + s] = tf20_fold_pre<KFLIP.a, KFLIP.b>(b1f + (unsigned)s, one, m29) <= FLIP_T;

    // Owners store raw values AFTER hashing (hides LDG->STG latency under
    // the hash stream); flipped slots overwritten after the fence.
    *reinterpret_cast<float4*>(out + i0) = v0;
    *reinterpret_cast<float4*>(out + i1) = v1;

    // Warp-uniform flip masks + prefix counts.
    unsigned m[8], cum[9];
    cum[0] = 0;
#pragma unroll
    for (int s = 0; s < 8; ++s) {
        m[s] = __ballot_sync(0xFFFFFFFFu, fl[s]);
        cum[s + 1] = cum[s] + (unsigned)__popc(m[s]);
    }
    unsigned nf = cum[8];

    __syncwarp();  // owner stores happen-before compacted overwrites

    // Compacted salt passes: 32 flips served per pass (~1 pass typical).
    for (unsigned start = 0; start < nf; start += 32u) {
        unsigned r = start + lane;
        if (r < nf) {
            unsigned mm = m[0], rbase = 0u, eoff = 0u;
#pragma unroll
            for (int w = 1; w < 8; ++w) {
                if (r >= cum[w]) {
                    mm = m[w];
                    rbase = cum[w];
                    eoff = (w < 4) ? (unsigned)w : (unsigned)w + 124u;
                }
            }
            unsigned rr = r - rbase;
            unsigned pos = 0u, c;
            c = (unsigned)__popc(mm & 0xFFFFu); if (rr >= c) { rr -= c; pos += 16u; mm >>= 16; }
            c = (unsigned)__popc(mm & 0xFFu);   if (rr >= c) { rr -= c; pos += 8u;  mm >>= 8; }
            c = (unsigned)__popc(mm & 0xFu);    if (rr >= c) { rr -= c; pos += 4u;  mm >>= 4; }
            c = (unsigned)__popc(mm & 0x3u);    if (rr >= c) { rr -= c; pos += 2u;  mm >>= 2; }
            c = mm & 1u;                        if (rr >= c) { pos += 1u; }

            unsigned gi = base + 4u * pos + eoff;
            unsigned bs = tf20_fold_pre<KSALT.a, KSALT.b>(
                madi<KSALT.b>(gi, one), one, m29);
            out[gi] = (bs <= SALT_T) ? 1.0f : 0.0f;
        }
    }
}

extern "C" void kernel_launch(void* const* d_in, const int* in_sizes, int n_in,
                              void* d_out, int out_size) {
    const float* img = (const float*)d_in[0];
    float* out = (float*)d_out;
    constexpr unsigned threads = N_TOTAL / 8u;    // 6291456
    constexpr unsigned blocks  = threads / 256u;  // 24576
    impulse_noise_kernel<<<blocks, 256>>>(img, out, 1u);
}

// round 17
// speedup vs baseline: 1.0168x; 1.0012x over previous
#include <cuda_runtime.h>
#include <stdint.h>

// ============================================================================
// ImpulseNoise — bit-exact JAX (threefry_partitionable) salt & pepper.
// key=(0,42); k_flip = tf20(key,(0,0)); k_salt = tf20(key,(0,1))
// bits(i) = fold(tf20(k, (0, i)));  u = (bits>>9)*2^-23
// u <= 0.09f  <=>  bits <= (754974<<9)|511     (rel_err=0, R2-R16)
// u <= 0.5    <=>  bits <= 0x800001FF
//
// FINAL (R13 config, confirmed twice: 158.3 / 158.0 us):
//   - k=2 mul-pair rotates (rounds 6,14 rot29): measured optimum of the
//     k-sweep {0:159.3, 2:158.3, 3:159.7, 5:162.9}
//   - all round adds forced to IMAD (fma pipe) via mad.lo + opaque `one`
//   - counter pre-add hoisted out of the chain loops
//   - hash-first / store-after ordering
//   - salt hashes warp-ballot-compacted: 0.09 hashes/elem instead of 1.0
//   - falsified levers: IMAD.WIDE rotates (issue-poison), injection folds
//     (alu saturation), occupancy pinning, manual lockstep ILP
// Residual gap to the ~155us structural floor: alu-pipe efficiency (~93%)
// and the ~81% issue band — invariant across all code shapes tested.
// ============================================================================

struct U2c { unsigned a, b; };

constexpr U2c threefry20_host(unsigned k0, unsigned k1, unsigned x0, unsigned x1) {
    unsigned ks2 = k0 ^ k1 ^ 0x1BD11BDAu;
    x0 += k0; x1 += k1;
#define TFR_H(r) { x0 += x1; x1 = (x1 << (r)) | (x1 >> (32 - (r))); x1 ^= x0; }
    TFR_H(13) TFR_H(15) TFR_H(26) TFR_H(6)
    x0 += k1;  x1 += ks2 + 1u;
    TFR_H(17) TFR_H(29) TFR_H(16) TFR_H(24)
    x0 += ks2; x1 += k0 + 2u;
    TFR_H(13) TFR_H(15) TFR_H(26) TFR_H(6)
    x0 += k0;  x1 += k1 + 3u;
    TFR_H(17) TFR_H(29) TFR_H(16) TFR_H(24)
    x0 += k1;  x1 += ks2 + 4u;
    TFR_H(13) TFR_H(15) TFR_H(26) TFR_H(6)
    x0 += ks2; x1 += k0 + 5u;
#undef TFR_H
    return U2c{x0, x1};
}

constexpr U2c KFLIP = threefry20_host(0u, 42u, 0u, 0u);
constexpr U2c KSALT = threefry20_host(0u, 42u, 0u, 1u);

constexpr unsigned N_TOTAL = 64u * 3u * 512u * 512u;   // 50331648
constexpr unsigned FLIP_T  = (754974u << 9) | 511u;    // u <= 0.09f
constexpr unsigned SALT_T  = 0x800001FFu;              // u <= 0.5f

// Adds forced to IMAD (fma pipe): d = a*one + b.
__device__ __forceinline__ unsigned madr(unsigned a, unsigned one, unsigned b) {
    unsigned d;
    asm("mad.lo.u32 %0, %1, %2, %3;" : "=r"(d) : "r"(a), "r"(one), "r"(b));
    return d;
}
template <unsigned IMM>
__device__ __forceinline__ unsigned madi(unsigned a, unsigned one) {
    unsigned d;
    asm("mad.lo.u32 %0, %1, %2, %3;" : "=r"(d) : "r"(a), "r"(one), "n"(IMM));
    return d;
}

// SHF round: add (fma) + funnel-rotate (alu) + xor (alu).
#define TFR_S(r) { x0 = madr(x0, one, x1); x1 = __funnelshift_l(x1, x1, (r)); x1 ^= x0; }
// MUL-PAIR round: add (fma) + mullo,mulhi (2x single-reg IMAD, fma) +
// fused (lo|hi)^x0 (ONE LOP3, alu).
#define TFR_M2(mr) { x0 = madr(x0, one, x1);            \
    unsigned lo = x1 * (mr);                             \
    unsigned hi = __umulhi(x1, (mr));                    \
    x1 = (lo | hi) ^ x0; }

// Threefry-2x32-20 with x1 counter-init PRE-ADDED (x1in = i + K1).
// Mul-pair rounds: 6 and 14 (rot 29). Returns x0^x1.
template <unsigned K0, unsigned K1>
__device__ __forceinline__ unsigned tf20_fold_pre(unsigned x1in, unsigned one,
                                                  unsigned m29) {
    constexpr unsigned KS2 = K0 ^ K1 ^ 0x1BD11BDAu;
    unsigned x1 = x1in;
    unsigned x0 = madi<K0>(x1, one);                 // round-1 add (x0_init=K0)
    x1 = __funnelshift_l(x1, x1, 13); x1 ^= x0;      // finish round 1
    TFR_S(15) TFR_S(26) TFR_S(6)                     // rounds 2,3,4
    x0 = madi<K1>(x0, one);   x1 = madi<KS2 + 1u>(x1, one);
    TFR_S(17) TFR_M2(m29) TFR_S(16) TFR_S(24)        // rounds 5,6,7,8
    x0 = madi<KS2>(x0, one);  x1 = madi<K0 + 2u>(x1, one);
    TFR_S(13) TFR_S(15) TFR_S(26) TFR_S(6)           // rounds 9-12
    x0 = madi<K0>(x0, one);   x1 = madi<K1 + 3u>(x1, one);
    TFR_S(17) TFR_M2(m29) TFR_S(16) TFR_S(24)        // rounds 13,14,15,16
    x0 = madi<K1>(x0, one);   x1 = madi<KS2 + 4u>(x1, one);
    TFR_S(13) TFR_S(15) TFR_S(26) TFR_S(6)           // rounds 17-20
    x0 = madi<KS2>(x0, one);  x1 = madi<K0 + 5u>(x1, one);
    return x0 ^ x1;
}
#undef TFR_S
#undef TFR_M2

// 8 elements per thread; warp covers 256 consecutive elements.
__global__ void __launch_bounds__(256)
impulse_noise_kernel(const float* __restrict__ img, float* __restrict__ out,
                     unsigned one) {
    unsigned m29 = one << 29;   // opaque 2^29 multiplier

    unsigned gwarp = (blockIdx.x * 256u + threadIdx.x) >> 5;
    unsigned lane  = threadIdx.x & 31u;
    unsigned base  = gwarp * 256u;
    unsigned i0 = base + 4u * lane;
    unsigned i1 = base + 128u + 4u * lane;

    float4 v0 = *reinterpret_cast<const float4*>(img + i0);
    float4 v1 = *reinterpret_cast<const float4*>(img + i1);

    // Hoisted counter bases: each chain's x1 init is one add from these.
    unsigned b0f = madi<KFLIP.b>(i0, one);   // i0 + K1_flip
    unsigned b1f = madi<KFLIP.b>(i1, one);   // i1 + K1_flip

    // Mandatory flip hashes (8 independent chains for ILP).
    bool fl[8];
#pragma unroll
    for (int s = 0; s < 4; ++s)
        fl[s] = tf20_fold_pre<KFLIP.a, KFLIP.b>(b0f + (unsigned)s, one, m29) <= FLIP_T;
#pragma unroll
    for (int s = 0; s < 4; ++s)
        fl[4 + s] = tf20_fold_pre<KFLIP.a, KFLIP.b>(b1f + (unsigned)s, one, m29) <= FLIP_T;

    // Owners store raw values AFTER hashing (hides LDG->STG latency under
    // the hash stream); flipped slots overwritten after the fence.
    *reinterpret_cast<float4*>(out + i0) = v0;
    *reinterpret_cast<float4*>(out + i1) = v1;

    // Warp-uniform flip masks + prefix counts.
    unsigned m[8], cum[9];
    cum[0] = 0;
#pragma unroll
    for (int s = 0; s < 8; ++s) {
        m[s] = __ballot_sync(0xFFFFFFFFu, fl[s]);
        cum[s + 1] = cum[s] + (unsigned)__popc(m[s]);
    }
    unsigned nf = cum[8];

    __syncwarp();  // owner stores happen-before compacted overwrites

    // Compacted salt passes: 32 flips served per pass (~1 pass typical).
    for (unsigned start = 0; start < nf; start += 32u) {
        unsigned r = start + lane;
        if (r < nf) {
            unsigned mm = m[0], rbase = 0u, eoff = 0u;
#pragma unroll
            for (int w = 1; w < 8; ++w) {
                if (r >= cum[w]) {
                    mm = m[w];
                    rbase = cum[w];
                    eoff = (w < 4) ? (unsigned)w : (unsigned)w + 124u;
                }
            }
            unsigned rr = r - rbase;
            unsigned pos = 0u, c;
            c = (unsigned)__popc(mm & 0xFFFFu); if (rr >= c) { rr -= c; pos += 16u; mm >>= 16; }
            c = (unsigned)__popc(mm & 0xFFu);   if (rr >= c) { rr -= c; pos += 8u;  mm >>= 8; }
            c = (unsigned)__popc(mm & 0xFu);    if (rr >= c) { rr -= c; pos += 4u;  mm >>= 4; }
            c = (unsigned)__popc(mm & 0x3u);    if (rr >= c) { rr -= c; pos += 2u;  mm >>= 2; }
            c = mm & 1u;                        if (rr >= c) { pos += 1u; }

            unsigned gi = base + 4u * pos + eoff;
            unsigned bs = tf20_fold_pre<KSALT.a, KSALT.b>(
                madi<KSALT.b>(gi, one), one, m29);
            out[gi] = (bs <= SALT_T) ? 1.0f : 0.0f;
        }
    }
}

extern "C" void kernel_launch(void* const* d_in, const int* in_sizes, int n_in,
                              void* d_out, int out_size) {
    const float* img = (const float*)d_in[0];
    float* out = (float*)d_out;
    constexpr unsigned threads = N_TOTAL / 8u;    // 6291456
    constexpr unsigned blocks  = threads / 256u;  // 24576
    impulse_noise_kernel<<<blocks, 256>>>(img, out, 1u);
}